// round 11
// baseline (speedup 1.0000x reference)
#include <cuda_runtime.h>
#include <math.h>
#include <stdint.h>

// Problem constants
#define BB   256          // batch
#define TT   128          // time steps
#define NINW 1024         // obs features
#define HH   512          // H1 == H2
#define EE   256          // GRU hidden
#define AA   16           // action dim
#define MROWS (TT*BB)     // 32768
#define KHE  (EE+AA)      // 272
#define NG   (3*EE)       // 768 (gate width)

// ---------------------------------------------------------------------------
// Device scratch (static __device__ arrays; no allocation anywhere)
// ---------------------------------------------------------------------------
__device__ float  d_X1[MROWS * HH];        // 64 MB
__device__ float  d_X2[MROWS * HH];        // 64 MB
__device__ float  d_GI[MROWS * NG];        // 96 MB  (ir|iz|in per row)
__device__ float  d_AE[TT * BB * AA];      // 2 MB   encoded actions
__device__ float  d_h[2][BB * EE];         // ping-pong hidden state
__device__ float4 d_Wq4[KHE * EE];         // [k][e] -> (whe, wr, wz, wn)
__device__ float4 d_bcg4[EE];              // (bhe, br, bz, bn)
__device__ float  d_Wfold[HH * NG];        // folded W3@Wih   (1.5 MB)
__device__ float  d_bfold[NG];             // folded b3@Wih + bih

__device__ __forceinline__ float* devBuf(int s) {
    switch (s) {
        case 1: return d_X1;
        case 2: return d_X2;
        default: return d_GI;
    }
}

// ---------------------------------------------------------------------------
// Prep: combined recurrent weights  Wq[k][e][g]
//   g=0 : Whe[k][e]                       (h_enc)
//   g=1..3 : sum_m Whe[k][m]*Whh[m][(g-1)*256+e]   (folded gh = h_enc@Whh)
// Plus combined bias bcg[e][g].
// grid: 272 blocks x 256 threads  (k = blockIdx.x, e = threadIdx.x)
// ---------------------------------------------------------------------------
__global__ void prep_wq(const float* __restrict__ Whe, const float* __restrict__ bhe,
                        const float* __restrict__ Whh, const float* __restrict__ bhh) {
    int k = blockIdx.x;
    int e = threadIdx.x;
    const float* wrow = Whe + (size_t)k * EE;
    float s1 = 0.f, s2 = 0.f, s3 = 0.f;
    #pragma unroll 4
    for (int m = 0; m < EE; m++) {
        float w = wrow[m];
        const float* hr = Whh + (size_t)m * NG;
        s1 = fmaf(w, hr[e],          s1);
        s2 = fmaf(w, hr[EE + e],     s2);
        s3 = fmaf(w, hr[2 * EE + e], s3);
    }
    d_Wq4[k * EE + e] = make_float4(wrow[e], s1, s2, s3);

    if (k == 0) {
        float t1 = 0.f, t2 = 0.f, t3 = 0.f;
        #pragma unroll 4
        for (int m = 0; m < EE; m++) {
            float bm = bhe[m];
            const float* hr = Whh + (size_t)m * NG;
            t1 = fmaf(bm, hr[e],          t1);
            t2 = fmaf(bm, hr[EE + e],     t2);
            t3 = fmaf(bm, hr[2 * EE + e], t3);
        }
        d_bcg4[e] = make_float4(bhe[e], t1 + bhh[e], t2 + bhh[EE + e], t3 + bhh[2 * EE + e]);
    }
}

// ---------------------------------------------------------------------------
// Prep: folded MLP tail  Wfold[k][j] = sum_m W3[k][m]*Wih[m][j]
//       bfold[j] = sum_m b3[m]*Wih[m][j] + bih[j]
// grid: (NG/256=3, HH=512), 256 threads  (j = col, k = blockIdx.y)
// ---------------------------------------------------------------------------
__global__ void prep_fold(const float* __restrict__ W3, const float* __restrict__ b3,
                          const float* __restrict__ Wih, const float* __restrict__ bih) {
    int j = blockIdx.x * 256 + threadIdx.x;   // 0..767
    int k = blockIdx.y;                        // 0..511
    const float* w3row = W3 + (size_t)k * EE;
    float s = 0.f;
    #pragma unroll 4
    for (int m = 0; m < EE; m++)
        s = fmaf(w3row[m], Wih[(size_t)m * NG + j], s);
    d_Wfold[(size_t)k * NG + j] = s;

    if (k == 0) {
        float t = bih[j];
        #pragma unroll 4
        for (int m = 0; m < EE; m++)
            t = fmaf(b3[m], Wih[(size_t)m * NG + j], t);
        d_bfold[j] = t;
    }
}

// ---------------------------------------------------------------------------
// Prep: encoded actions AE[t][b][j] = actions[b][t][:]@Wae + bae
// grid: 2048 x 256 (one thread per output)
// ---------------------------------------------------------------------------
__global__ void prep_ae(const float* __restrict__ actions,
                        const float* __restrict__ Wae, const float* __restrict__ bae) {
    int gid = blockIdx.x * 256 + threadIdx.x;        // (t*256+b)*16 + j
    int j = gid & 15;
    int b = (gid >> 4) & 255;
    int t = gid >> 12;
    const float* arow = actions + ((size_t)b * TT + t) * AA;
    float s = bae[j];
    #pragma unroll
    for (int k = 0; k < AA; k++) s = fmaf(arow[k], Wae[k * AA + j], s);
    d_AE[gid] = s;
}

// ---------------------------------------------------------------------------
// SGEMM: C[M,N] = A[M,K] @ W[K,N] + bias  (fp32, 128x128x8 tile, 8x8/thread)
// amode==1: logical row tb=(t*256+b) maps to obs row (b*128+t), K=NIN
// aSel/cSel pick device scratch buffers (Ain overrides aSel when non-null)
// W==nullptr -> d_Wfold, bias==nullptr -> d_bfold
// ---------------------------------------------------------------------------
__global__ void __launch_bounds__(256, 2)
sgemm_k(const float* __restrict__ Ain, int aSel,
        const float* __restrict__ Win, const float* __restrict__ biasIn,
        int cSel, int M, int N, int K, int amode) {
    __shared__ float As[8][128];
    __shared__ float Bs[8][128];

    const float* A = Ain ? Ain : devBuf(aSel);
    const float* W = Win ? Win : d_Wfold;
    const float* bias = biasIn ? biasIn : d_bfold;
    float* C = devBuf(cSel);

    int tid  = threadIdx.x;
    int row0 = blockIdx.y * 128;
    int col0 = blockIdx.x * 128;
    int tx = tid & 15;        // 0..15 -> 8 cols each
    int ty = tid >> 4;        // 0..15 -> 8 rows each

    // A tile load indices: 1 float4 per thread
    int arow = tid >> 1;            // 0..127
    int acol = (tid & 1) * 4;       // 0 or 4
    const float* Abase;
    if (amode == 1) {
        int tb = row0 + arow;
        int t = tb >> 8, b = tb & 255;
        Abase = A + ((size_t)b * TT + t) * NINW;
    } else {
        Abase = A + (size_t)(row0 + arow) * K;
    }
    // B tile load indices: 1 float4 per thread
    int brow = tid >> 5;            // 0..7
    int bcol = (tid & 31) * 4;      // 0..124

    float acc[8][8];
    #pragma unroll
    for (int i = 0; i < 8; i++)
        #pragma unroll
        for (int j = 0; j < 8; j++) acc[i][j] = 0.f;

    for (int k0 = 0; k0 < K; k0 += 8) {
        float4 av = *(const float4*)(Abase + k0 + acol);
        As[acol + 0][arow] = av.x;
        As[acol + 1][arow] = av.y;
        As[acol + 2][arow] = av.z;
        As[acol + 3][arow] = av.w;
        *(float4*)&Bs[brow][bcol] =
            *(const float4*)(W + (size_t)(k0 + brow) * N + col0 + bcol);
        __syncthreads();

        #pragma unroll
        for (int kk = 0; kk < 8; kk++) {
            float a[8], bb[8];
            *(float4*)&a[0]  = *(const float4*)&As[kk][ty * 8];
            *(float4*)&a[4]  = *(const float4*)&As[kk][ty * 8 + 4];
            *(float4*)&bb[0] = *(const float4*)&Bs[kk][tx * 8];
            *(float4*)&bb[4] = *(const float4*)&Bs[kk][tx * 8 + 4];
            #pragma unroll
            for (int i = 0; i < 8; i++)
                #pragma unroll
                for (int j = 0; j < 8; j++)
                    acc[i][j] = fmaf(a[i], bb[j], acc[i][j]);
        }
        __syncthreads();
    }

    float bia[8];
    #pragma unroll
    for (int j = 0; j < 8; j++) bia[j] = bias[col0 + tx * 8 + j];

    #pragma unroll
    for (int i = 0; i < 8; i++) {
        size_t r = (size_t)(row0 + ty * 8 + i);
        float* cp = C + r * N + col0 + tx * 8;
        float4 v0 = make_float4(acc[i][0] + bia[0], acc[i][1] + bia[1],
                                acc[i][2] + bia[2], acc[i][3] + bia[3]);
        float4 v1 = make_float4(acc[i][4] + bia[4], acc[i][5] + bia[5],
                                acc[i][6] + bia[6], acc[i][7] + bia[7]);
        *(float4*)(cp)     = v0;
        *(float4*)(cp + 4) = v1;
    }
}

// ---------------------------------------------------------------------------
// Fused per-timestep BatchNorm (training stats over B=256) + ELU, in place.
// grid: (T=128, H/64=8), block 256 threads (64 features x 4 batch-groups)
// ---------------------------------------------------------------------------
__global__ void bn_elu(int sel, const float* __restrict__ g, const float* __restrict__ be) {
    float* X = devBuf(sel);
    int t  = blockIdx.x;
    int jl = threadIdx.x & 63;
    int grp = threadIdx.x >> 6;                 // 0..3
    int j = blockIdx.y * 64 + jl;

    float s = 0.f, s2 = 0.f;
    int brow0 = grp * 64;
    #pragma unroll 4
    for (int b = brow0; b < brow0 + 64; b++) {
        float v = X[((size_t)t * BB + b) * HH + j];
        s += v;
        s2 = fmaf(v, v, s2);
    }
    __shared__ float ss[4][64], sq[4][64], mu[64], rs[64];
    ss[grp][jl] = s;
    sq[grp][jl] = s2;
    __syncthreads();
    if (threadIdx.x < 64) {
        float S  = ss[0][jl] + ss[1][jl] + ss[2][jl] + ss[3][jl];
        float S2 = sq[0][jl] + sq[1][jl] + sq[2][jl] + sq[3][jl];
        float m = S * (1.f / 256.f);
        float var = S2 * (1.f / 256.f) - m * m;
        mu[jl] = m;
        rs[jl] = rsqrtf(var + 1e-5f);
    }
    __syncthreads();
    float m = mu[jl], r = rs[jl], gg = g[j], bb = be[j];
    #pragma unroll 4
    for (int b = brow0; b < brow0 + 64; b++) {
        size_t idx = ((size_t)t * BB + b) * HH + j;
        float v = gg * (X[idx] - m) * r + bb;
        X[idx] = v > 0.f ? v : expm1f(v);
    }
}

// ---------------------------------------------------------------------------
// Recurrence step (one launch per timestep):
//   A = [h_prev | a_prev]  (32 rows x 272 in smem)
//   4-gate fused GEMM vs Wq (gate-packed float4), then GRU elementwise.
// grid: (E/16=16, B/32=8) = 128 blocks; block (16,8) = 128 threads
// thread: 1 e-column, 4 b-rows, 4 gates
// ---------------------------------------------------------------------------
__global__ void __launch_bounds__(128)
step_kernel(int t, float* __restrict__ outFinal) {
    __shared__ float As[32][276];     // stride 276 -> 16B-aligned rows, conflict-spread

    int tx = threadIdx.x;             // 0..15 -> e
    int ty = threadIdx.y;             // 0..7  -> 4 b rows each
    int tid = ty * 16 + tx;
    int e  = blockIdx.x * 16 + tx;
    int b0 = blockIdx.y * 32;

    const float* hprev = d_h[t & 1];
    // h part of A
    for (int i = tid; i < 32 * 256; i += 128) {
        int r = i >> 8, c = i & 255;
        As[r][c] = (t == 0) ? 0.f : hprev[(b0 + r) * EE + c];
    }
    // a_prev part of A (encoded action of previous step)
    for (int i = tid; i < 32 * 16; i += 128) {
        int r = i >> 4, c = i & 15;
        As[r][256 + c] = (t == 0) ? 0.f
                         : d_AE[(((size_t)(t - 1) * BB) + b0 + r) * AA + c];
    }
    __syncthreads();

    float4 acc[4];
    #pragma unroll
    for (int r = 0; r < 4; r++) acc[r] = make_float4(0.f, 0.f, 0.f, 0.f);

    const float4* Wq = d_Wq4;
    for (int k = 0; k < KHE; k += 4) {
        float a[4][4];
        #pragma unroll
        for (int r = 0; r < 4; r++)
            *(float4*)&a[r][0] = *(const float4*)&As[ty * 4 + r][k];
        #pragma unroll
        for (int i = 0; i < 4; i++) {
            float4 w = Wq[(k + i) * EE + e];
            #pragma unroll
            for (int r = 0; r < 4; r++) {
                acc[r].x = fmaf(a[r][i], w.x, acc[r].x);
                acc[r].y = fmaf(a[r][i], w.y, acc[r].y);
                acc[r].z = fmaf(a[r][i], w.z, acc[r].z);
                acc[r].w = fmaf(a[r][i], w.w, acc[r].w);
            }
        }
    }

    float4 bc = d_bcg4[e];
    float* out = (t == TT - 1) ? outFinal : d_h[(t + 1) & 1];
    const float* GIt = d_GI + (size_t)t * BB * NG;

    #pragma unroll
    for (int r = 0; r < 4; r++) {
        int b = b0 + ty * 4 + r;
        float henc = acc[r].x + bc.x;
        float hr   = acc[r].y + bc.y;
        float hz   = acc[r].z + bc.z;
        float hn   = acc[r].w + bc.w;
        const float* gi = GIt + (size_t)b * NG;
        float ir = gi[e], iz = gi[EE + e], inn = gi[2 * EE + e];
        float rg = 1.f / (1.f + expf(-(ir + hr)));
        float zg = 1.f / (1.f + expf(-(iz + hz)));
        float ng = tanhf(inn + rg * hn);
        out[b * EE + e] = (1.f - zg) * ng + zg * henc;
    }
}

// ---------------------------------------------------------------------------
// Host launch (graph-capturable: kernel launches only)
// ---------------------------------------------------------------------------
extern "C" void kernel_launch(void* const* d_in, const int* in_sizes, int n_in,
                              void* d_out, int out_size) {
    const float* obs     = (const float*)d_in[0];
    const float* actions = (const float*)d_in[1];
    const float* W1  = (const float*)d_in[2];
    const float* b1  = (const float*)d_in[3];
    const float* g1  = (const float*)d_in[4];
    const float* be1 = (const float*)d_in[5];
    const float* W2  = (const float*)d_in[6];
    const float* b2  = (const float*)d_in[7];
    const float* g2  = (const float*)d_in[8];
    const float* be2 = (const float*)d_in[9];
    const float* W3  = (const float*)d_in[10];
    const float* b3  = (const float*)d_in[11];
    const float* Wih = (const float*)d_in[12];
    const float* bih = (const float*)d_in[13];
    const float* Whh = (const float*)d_in[14];
    const float* bhh = (const float*)d_in[15];
    const float* Whe = (const float*)d_in[16];
    const float* bhe = (const float*)d_in[17];
    const float* Wae = (const float*)d_in[18];
    const float* bae = (const float*)d_in[19];
    float* out = (float*)d_out;

    // One-time-per-launch prep (recomputed every call: deterministic)
    prep_wq<<<KHE, 256>>>(Whe, bhe, Whh, bhh);
    prep_fold<<<dim3(NG / 256, HH), 256>>>(W3, b3, Wih, bih);
    prep_ae<<<(TT * BB * AA) / 256, 256>>>(actions, Wae, bae);

    // Batched MLP + GRU input path (all timesteps in parallel)
    sgemm_k<<<dim3(HH / 128, MROWS / 128), 256>>>(obs, 0, W1, b1, 1, MROWS, HH, NINW, 1);
    bn_elu<<<dim3(TT, HH / 64), 256>>>(1, g1, be1);
    sgemm_k<<<dim3(HH / 128, MROWS / 128), 256>>>(nullptr, 1, W2, b2, 2, MROWS, HH, HH, 0);
    bn_elu<<<dim3(TT, HH / 64), 256>>>(2, g2, be2);
    // Folded (W3@Wih) GEMM: X2 -> GI directly
    sgemm_k<<<dim3(NG / 128, MROWS / 128), 256>>>(nullptr, 2, nullptr, nullptr, 4, MROWS, NG, HH, 0);

    // Sequential GRU recurrence (one fused GEMM+gate kernel per step)
    for (int t = 0; t < TT; t++)
        step_kernel<<<dim3(EE / 16, BB / 32), dim3(16, 8)>>>(t, out);
}

// round 14
// speedup vs baseline: 1.1197x; 1.1197x over previous
#include <cuda_runtime.h>
#include <math.h>
#include <stdint.h>

// Problem constants
#define BB   256          // batch
#define TT   128          // time steps
#define NINW 1024         // obs features
#define HH   512          // H1 == H2
#define EE   256          // GRU hidden
#define AA   16           // action dim
#define MROWS (TT*BB)     // 32768
#define KHE  (EE+AA)      // 272
#define NG   (3*EE)       // 768 (gate width)

// ---------------------------------------------------------------------------
// Device scratch (static __device__ arrays; no allocation anywhere)
// ---------------------------------------------------------------------------
__device__ float  d_X1[MROWS * HH];        // 64 MB
__device__ float  d_X2[MROWS * HH];        // 64 MB
__device__ float  d_GI[MROWS * NG];        // 96 MB  (ir|iz|in per row)
__device__ float  d_AE[TT * BB * AA];      // 2 MB   encoded actions
__device__ float4 d_Wq4[KHE * EE];         // [k][e] -> (whe, wr, wz, wn)
__device__ float4 d_bcg4[EE];              // (bhe, br, bz, bn)
__device__ float  d_Wfold[HH * NG];        // folded W3@Wih   (1.5 MB)
__device__ float  d_bfold[NG];             // folded b3@Wih + bih

__device__ __forceinline__ float* devBuf(int s) {
    switch (s) {
        case 1: return d_X1;
        case 2: return d_X2;
        default: return d_GI;
    }
}

// ---------------------------------------------------------------------------
// Prep: combined recurrent weights  Wq[k][e][g]
//   g=0 : Whe[k][e]                       (h_enc)
//   g=1..3 : sum_m Whe[k][m]*Whh[m][(g-1)*256+e]   (folded gh = h_enc@Whh)
// Plus combined bias bcg[e][g].
// ---------------------------------------------------------------------------
__global__ void prep_wq(const float* __restrict__ Whe, const float* __restrict__ bhe,
                        const float* __restrict__ Whh, const float* __restrict__ bhh) {
    int k = blockIdx.x;
    int e = threadIdx.x;
    const float* wrow = Whe + (size_t)k * EE;
    float s1 = 0.f, s2 = 0.f, s3 = 0.f;
    #pragma unroll 4
    for (int m = 0; m < EE; m++) {
        float w = wrow[m];
        const float* hr = Whh + (size_t)m * NG;
        s1 = fmaf(w, hr[e],          s1);
        s2 = fmaf(w, hr[EE + e],     s2);
        s3 = fmaf(w, hr[2 * EE + e], s3);
    }
    d_Wq4[k * EE + e] = make_float4(wrow[e], s1, s2, s3);

    if (k == 0) {
        float t1 = 0.f, t2 = 0.f, t3 = 0.f;
        #pragma unroll 4
        for (int m = 0; m < EE; m++) {
            float bm = bhe[m];
            const float* hr = Whh + (size_t)m * NG;
            t1 = fmaf(bm, hr[e],          t1);
            t2 = fmaf(bm, hr[EE + e],     t2);
            t3 = fmaf(bm, hr[2 * EE + e], t3);
        }
        d_bcg4[e] = make_float4(bhe[e], t1 + bhh[e], t2 + bhh[EE + e], t3 + bhh[2 * EE + e]);
    }
}

// ---------------------------------------------------------------------------
// Prep: folded MLP tail  Wfold[k][j] = sum_m W3[k][m]*Wih[m][j]
//       bfold[j] = sum_m b3[m]*Wih[m][j] + bih[j]
// ---------------------------------------------------------------------------
__global__ void prep_fold(const float* __restrict__ W3, const float* __restrict__ b3,
                          const float* __restrict__ Wih, const float* __restrict__ bih) {
    int j = blockIdx.x * 256 + threadIdx.x;   // 0..767
    int k = blockIdx.y;                        // 0..511
    const float* w3row = W3 + (size_t)k * EE;
    float s = 0.f;
    #pragma unroll 4
    for (int m = 0; m < EE; m++)
        s = fmaf(w3row[m], Wih[(size_t)m * NG + j], s);
    d_Wfold[(size_t)k * NG + j] = s;

    if (k == 0) {
        float t = bih[j];
        #pragma unroll 4
        for (int m = 0; m < EE; m++)
            t = fmaf(b3[m], Wih[(size_t)m * NG + j], t);
        d_bfold[j] = t;
    }
}

// ---------------------------------------------------------------------------
// Prep: encoded actions AE[t][b][j] = actions[b][t][:]@Wae + bae
// ---------------------------------------------------------------------------
__global__ void prep_ae(const float* __restrict__ actions,
                        const float* __restrict__ Wae, const float* __restrict__ bae) {
    int gid = blockIdx.x * 256 + threadIdx.x;        // (t*256+b)*16 + j
    int j = gid & 15;
    int b = (gid >> 4) & 255;
    int t = gid >> 12;
    const float* arow = actions + ((size_t)b * TT + t) * AA;
    float s = bae[j];
    #pragma unroll
    for (int k = 0; k < AA; k++) s = fmaf(arow[k], Wae[k * AA + j], s);
    d_AE[gid] = s;
}

// ---------------------------------------------------------------------------
// SGEMM: C[M,N] = A[M,K] @ W[K,N] + bias  (fp32, 128x128x8 tile, 8x8/thread)
// amode==1: logical row tb=(t*256+b) maps to obs row (b*128+t), K=NIN
// W==nullptr -> d_Wfold, bias==nullptr -> d_bfold
// ---------------------------------------------------------------------------
__global__ void __launch_bounds__(256, 2)
sgemm_k(const float* __restrict__ Ain, int aSel,
        const float* __restrict__ Win, const float* __restrict__ biasIn,
        int cSel, int M, int N, int K, int amode) {
    __shared__ float As[8][128];
    __shared__ float Bs[8][128];

    const float* A = Ain ? Ain : devBuf(aSel);
    const float* W = Win ? Win : d_Wfold;
    const float* bias = biasIn ? biasIn : d_bfold;
    float* C = devBuf(cSel);

    int tid  = threadIdx.x;
    int row0 = blockIdx.y * 128;
    int col0 = blockIdx.x * 128;
    int tx = tid & 15;
    int ty = tid >> 4;

    int arow = tid >> 1;
    int acol = (tid & 1) * 4;
    const float* Abase;
    if (amode == 1) {
        int tb = row0 + arow;
        int t = tb >> 8, b = tb & 255;
        Abase = A + ((size_t)b * TT + t) * NINW;
    } else {
        Abase = A + (size_t)(row0 + arow) * K;
    }
    int brow = tid >> 5;
    int bcol = (tid & 31) * 4;

    float acc[8][8];
    #pragma unroll
    for (int i = 0; i < 8; i++)
        #pragma unroll
        for (int j = 0; j < 8; j++) acc[i][j] = 0.f;

    for (int k0 = 0; k0 < K; k0 += 8) {
        float4 av = *(const float4*)(Abase + k0 + acol);
        As[acol + 0][arow] = av.x;
        As[acol + 1][arow] = av.y;
        As[acol + 2][arow] = av.z;
        As[acol + 3][arow] = av.w;
        *(float4*)&Bs[brow][bcol] =
            *(const float4*)(W + (size_t)(k0 + brow) * N + col0 + bcol);
        __syncthreads();

        #pragma unroll
        for (int kk = 0; kk < 8; kk++) {
            float a[8], bb[8];
            *(float4*)&a[0]  = *(const float4*)&As[kk][ty * 8];
            *(float4*)&a[4]  = *(const float4*)&As[kk][ty * 8 + 4];
            *(float4*)&bb[0] = *(const float4*)&Bs[kk][tx * 8];
            *(float4*)&bb[4] = *(const float4*)&Bs[kk][tx * 8 + 4];
            #pragma unroll
            for (int i = 0; i < 8; i++)
                #pragma unroll
                for (int j = 0; j < 8; j++)
                    acc[i][j] = fmaf(a[i], bb[j], acc[i][j]);
        }
        __syncthreads();
    }

    float bia[8];
    #pragma unroll
    for (int j = 0; j < 8; j++) bia[j] = bias[col0 + tx * 8 + j];

    #pragma unroll
    for (int i = 0; i < 8; i++) {
        size_t r = (size_t)(row0 + ty * 8 + i);
        float* cp = C + r * N + col0 + tx * 8;
        float4 v0 = make_float4(acc[i][0] + bia[0], acc[i][1] + bia[1],
                                acc[i][2] + bia[2], acc[i][3] + bia[3]);
        float4 v1 = make_float4(acc[i][4] + bia[4], acc[i][5] + bia[5],
                                acc[i][6] + bia[6], acc[i][7] + bia[7]);
        *(float4*)(cp)     = v0;
        *(float4*)(cp + 4) = v1;
    }
}

// ---------------------------------------------------------------------------
// Fused per-timestep BatchNorm (training stats over B=256) + ELU, in place.
// ---------------------------------------------------------------------------
__global__ void bn_elu(int sel, const float* __restrict__ g, const float* __restrict__ be) {
    float* X = devBuf(sel);
    int t  = blockIdx.x;
    int jl = threadIdx.x & 63;
    int grp = threadIdx.x >> 6;
    int j = blockIdx.y * 64 + jl;

    float s = 0.f, s2 = 0.f;
    int brow0 = grp * 64;
    #pragma unroll 4
    for (int b = brow0; b < brow0 + 64; b++) {
        float v = X[((size_t)t * BB + b) * HH + j];
        s += v;
        s2 = fmaf(v, v, s2);
    }
    __shared__ float ss[4][64], sq[4][64], mu[64], rs[64];
    ss[grp][jl] = s;
    sq[grp][jl] = s2;
    __syncthreads();
    if (threadIdx.x < 64) {
        float S  = ss[0][jl] + ss[1][jl] + ss[2][jl] + ss[3][jl];
        float S2 = sq[0][jl] + sq[1][jl] + sq[2][jl] + sq[3][jl];
        float m = S * (1.f / 256.f);
        float var = S2 * (1.f / 256.f) - m * m;
        mu[jl] = m;
        rs[jl] = rsqrtf(var + 1e-5f);
    }
    __syncthreads();
    float m = mu[jl], r = rs[jl], gg = g[j], bb = be[j];
    #pragma unroll 4
    for (int b = brow0; b < brow0 + 64; b++) {
        size_t idx = ((size_t)t * BB + b) * HH + j;
        float v = gg * (X[idx] - m) * r + bb;
        X[idx] = v > 0.f ? v : expm1f(v);
    }
}

// ---------------------------------------------------------------------------
// FUSED recurrence: one persistent kernel, batch-partitioned (GRU is diagonal
// in batch once GI/AE are precomputed). grid=64 blocks, each owns 4 batch
// rows and loops t=0..127 with h (+a_prev) in shared memory. No inter-block
// dependency -> no grid sync needed.
// 256 threads: thread e owns column e, 4 gates (float4 Wq), 4 batch rows.
// ---------------------------------------------------------------------------
__global__ void __launch_bounds__(256, 1)
gru_fused(float* __restrict__ outFinal) {
    __shared__ float hA[4][288];     // [b-row][k]  k<256: h, 256..271: a_prev

    const int e  = threadIdx.x;      // 0..255
    const int b0 = blockIdx.x * 4;

    // init h=0, a_prev=0
    #pragma unroll
    for (int r = 0; r < 4; r++) {
        hA[r][e] = 0.f;
        if (e < 32) hA[r][256 + (e & 15)] = 0.f;   // harmless double-write of zeros
    }
    __syncthreads();

    const float4 bc = d_bcg4[e];
    const float4* __restrict__ Wq = d_Wq4;

    for (int t = 0; t < TT; t++) {
        // gates: acc[r] = sum_k hA[r][k] * Wq[k][e]   (4 gates packed in float4)
        float4 acc0 = make_float4(0.f, 0.f, 0.f, 0.f);
        float4 acc1 = acc0, acc2 = acc0, acc3 = acc0;

        #pragma unroll 4
        for (int k = 0; k < KHE; k++) {
            float4 w = Wq[k * EE + e];
            float a0 = hA[0][k], a1 = hA[1][k], a2 = hA[2][k], a3 = hA[3][k];
            acc0.x = fmaf(a0, w.x, acc0.x); acc0.y = fmaf(a0, w.y, acc0.y);
            acc0.z = fmaf(a0, w.z, acc0.z); acc0.w = fmaf(a0, w.w, acc0.w);
            acc1.x = fmaf(a1, w.x, acc1.x); acc1.y = fmaf(a1, w.y, acc1.y);
            acc1.z = fmaf(a1, w.z, acc1.z); acc1.w = fmaf(a1, w.w, acc1.w);
            acc2.x = fmaf(a2, w.x, acc2.x); acc2.y = fmaf(a2, w.y, acc2.y);
            acc2.z = fmaf(a2, w.z, acc2.z); acc2.w = fmaf(a2, w.w, acc2.w);
            acc3.x = fmaf(a3, w.x, acc3.x); acc3.y = fmaf(a3, w.y, acc3.y);
            acc3.z = fmaf(a3, w.z, acc3.z); acc3.w = fmaf(a3, w.w, acc3.w);
        }

        // GRU elementwise per batch row
        float hnew[4];
        const float* GIt = d_GI + (size_t)t * BB * NG;
        {
            float4 acc[4] = {acc0, acc1, acc2, acc3};
            #pragma unroll
            for (int r = 0; r < 4; r++) {
                int b = b0 + r;
                float henc = acc[r].x + bc.x;
                float hr   = acc[r].y + bc.y;
                float hz   = acc[r].z + bc.z;
                float hn   = acc[r].w + bc.w;
                const float* gi = GIt + (size_t)b * NG;
                float ir = gi[e], iz = gi[EE + e], inn = gi[2 * EE + e];
                float rg = 1.f / (1.f + expf(-(ir + hr)));
                float zg = 1.f / (1.f + expf(-(iz + hz)));
                float ng = tanhf(inn + rg * hn);
                hnew[r] = (1.f - zg) * ng + zg * henc;
            }
        }

        if (t == TT - 1) {
            #pragma unroll
            for (int r = 0; r < 4; r++)
                outFinal[(size_t)(b0 + r) * EE + e] = hnew[r];
            break;
        }

        __syncthreads();             // all reads of hA done
        #pragma unroll
        for (int r = 0; r < 4; r++) hA[r][e] = hnew[r];
        // a_prev for step t+1 is AE[t]
        if (e < 64) {
            int r = e >> 4, c = e & 15;
            hA[r][256 + c] = d_AE[((size_t)t * BB + b0 + r) * AA + c];
        }
        __syncthreads();
    }
}

// ---------------------------------------------------------------------------
// Host launch (graph-capturable: kernel launches only)
// ---------------------------------------------------------------------------
extern "C" void kernel_launch(void* const* d_in, const int* in_sizes, int n_in,
                              void* d_out, int out_size) {
    const float* obs     = (const float*)d_in[0];
    const float* actions = (const float*)d_in[1];
    const float* W1  = (const float*)d_in[2];
    const float* b1  = (const float*)d_in[3];
    const float* g1  = (const float*)d_in[4];
    const float* be1 = (const float*)d_in[5];
    const float* W2  = (const float*)d_in[6];
    const float* b2  = (const float*)d_in[7];
    const float* g2  = (const float*)d_in[8];
    const float* be2 = (const float*)d_in[9];
    const float* W3  = (const float*)d_in[10];
    const float* b3  = (const float*)d_in[11];
    const float* Wih = (const float*)d_in[12];
    const float* bih = (const float*)d_in[13];
    const float* Whh = (const float*)d_in[14];
    const float* bhh = (const float*)d_in[15];
    const float* Whe = (const float*)d_in[16];
    const float* bhe = (const float*)d_in[17];
    const float* Wae = (const float*)d_in[18];
    const float* bae = (const float*)d_in[19];
    float* out = (float*)d_out;

    // One-time-per-launch prep (recomputed every call: deterministic)
    prep_wq<<<KHE, 256>>>(Whe, bhe, Whh, bhh);
    prep_fold<<<dim3(NG / 256, HH), 256>>>(W3, b3, Wih, bih);
    prep_ae<<<(TT * BB * AA) / 256, 256>>>(actions, Wae, bae);

    // Batched MLP + GRU input path (all timesteps in parallel)
    sgemm_k<<<dim3(HH / 128, MROWS / 128), 256>>>(obs, 0, W1, b1, 1, MROWS, HH, NINW, 1);
    bn_elu<<<dim3(TT, HH / 64), 256>>>(1, g1, be1);
    sgemm_k<<<dim3(HH / 128, MROWS / 128), 256>>>(nullptr, 1, W2, b2, 2, MROWS, HH, HH, 0);
    bn_elu<<<dim3(TT, HH / 64), 256>>>(2, g2, be2);
    // Folded (W3@Wih) GEMM: X2 -> GI directly
    sgemm_k<<<dim3(NG / 128, MROWS / 128), 256>>>(nullptr, 2, nullptr, nullptr, 4, MROWS, NG, HH, 0);

    // Entire GRU recurrence in ONE persistent kernel (batch-diagonal)
    gru_fused<<<64, 256>>>(out);
}

// round 15
// speedup vs baseline: 1.2201x; 1.0896x over previous
#include <cuda_runtime.h>
#include <math.h>
#include <stdint.h>

// Problem constants
#define BB   256          // batch
#define TT   128          // time steps
#define NINW 1024         // obs features
#define HH   512          // H1 == H2
#define EE   256          // GRU hidden
#define AA   16           // action dim
#define MROWS (TT*BB)     // 32768
#define KHE  (EE+AA)      // 272
#define NG   (3*EE)       // 768 (gate width)

// ---------------------------------------------------------------------------
// Device scratch (static __device__ arrays; no allocation anywhere)
// ---------------------------------------------------------------------------
__device__ float  d_X1[MROWS * HH];        // 64 MB
__device__ float  d_X2[MROWS * HH];        // 64 MB
__device__ float  d_GI[MROWS * NG];        // 96 MB  (ir|iz|in per row)
__device__ float  d_AE[TT * BB * AA];      // 2 MB   encoded actions
__device__ float4 d_Wq4[KHE * EE];         // [k][e] -> (whe, wr, wz, wn)
__device__ float4 d_bcg4[EE];              // (bhe, br, bz, bn)
__device__ float  d_Wfold[HH * NG];        // folded W3@Wih   (1.5 MB)
__device__ float  d_bfold[NG];             // folded b3@Wih + bih

__device__ __forceinline__ float* devBuf(int s) {
    switch (s) {
        case 1: return d_X1;
        case 2: return d_X2;
        default: return d_GI;
    }
}

// ---------------------------------------------------------------------------
// Prep: combined recurrent weights  Wq[k][e][g]
// ---------------------------------------------------------------------------
__global__ void prep_wq(const float* __restrict__ Whe, const float* __restrict__ bhe,
                        const float* __restrict__ Whh, const float* __restrict__ bhh) {
    int k = blockIdx.x;
    int e = threadIdx.x;
    const float* wrow = Whe + (size_t)k * EE;
    float s1 = 0.f, s2 = 0.f, s3 = 0.f;
    #pragma unroll 4
    for (int m = 0; m < EE; m++) {
        float w = wrow[m];
        const float* hr = Whh + (size_t)m * NG;
        s1 = fmaf(w, hr[e],          s1);
        s2 = fmaf(w, hr[EE + e],     s2);
        s3 = fmaf(w, hr[2 * EE + e], s3);
    }
    d_Wq4[k * EE + e] = make_float4(wrow[e], s1, s2, s3);

    if (k == 0) {
        float t1 = 0.f, t2 = 0.f, t3 = 0.f;
        #pragma unroll 4
        for (int m = 0; m < EE; m++) {
            float bm = bhe[m];
            const float* hr = Whh + (size_t)m * NG;
            t1 = fmaf(bm, hr[e],          t1);
            t2 = fmaf(bm, hr[EE + e],     t2);
            t3 = fmaf(bm, hr[2 * EE + e], t3);
        }
        d_bcg4[e] = make_float4(bhe[e], t1 + bhh[e], t2 + bhh[EE + e], t3 + bhh[2 * EE + e]);
    }
}

// ---------------------------------------------------------------------------
// Prep: folded MLP tail  Wfold = W3@Wih ; bfold = b3@Wih + bih
// ---------------------------------------------------------------------------
__global__ void prep_fold(const float* __restrict__ W3, const float* __restrict__ b3,
                          const float* __restrict__ Wih, const float* __restrict__ bih) {
    int j = blockIdx.x * 256 + threadIdx.x;   // 0..767
    int k = blockIdx.y;                        // 0..511
    const float* w3row = W3 + (size_t)k * EE;
    float s = 0.f;
    #pragma unroll 4
    for (int m = 0; m < EE; m++)
        s = fmaf(w3row[m], Wih[(size_t)m * NG + j], s);
    d_Wfold[(size_t)k * NG + j] = s;

    if (k == 0) {
        float t = bih[j];
        #pragma unroll 4
        for (int m = 0; m < EE; m++)
            t = fmaf(b3[m], Wih[(size_t)m * NG + j], t);
        d_bfold[j] = t;
    }
}

// ---------------------------------------------------------------------------
// Prep: encoded actions AE[t][b][j] = actions[b][t][:]@Wae + bae
// ---------------------------------------------------------------------------
__global__ void prep_ae(const float* __restrict__ actions,
                        const float* __restrict__ Wae, const float* __restrict__ bae) {
    int gid = blockIdx.x * 256 + threadIdx.x;        // (t*256+b)*16 + j
    int j = gid & 15;
    int b = (gid >> 4) & 255;
    int t = gid >> 12;
    const float* arow = actions + ((size_t)b * TT + t) * AA;
    float s = bae[j];
    #pragma unroll
    for (int k = 0; k < AA; k++) s = fmaf(arow[k], Wae[k * AA + j], s);
    d_AE[gid] = s;
}

// ---------------------------------------------------------------------------
// SGEMM: C[M,N] = A[M,K] @ W[K,N] + bias  (fp32, 128x128x8 tile, 8x8/thread)
// Software-pipelined: next chunk's global loads issued in registers during
// current chunk's FMAs; stored to smem only after the read-sync.
// amode==1: logical row tb=(t*256+b) maps to obs row (b*128+t), K=NIN
// W==nullptr -> d_Wfold, bias==nullptr -> d_bfold
// ---------------------------------------------------------------------------
__global__ void __launch_bounds__(256, 2)
sgemm_k(const float* __restrict__ Ain, int aSel,
        const float* __restrict__ Win, const float* __restrict__ biasIn,
        int cSel, int M, int N, int K, int amode) {
    __shared__ float As[8][128];
    __shared__ float Bs[8][128];

    const float* A = Ain ? Ain : devBuf(aSel);
    const float* W = Win ? Win : d_Wfold;
    const float* bias = biasIn ? biasIn : d_bfold;
    float* C = devBuf(cSel);

    int tid  = threadIdx.x;
    int row0 = blockIdx.y * 128;
    int col0 = blockIdx.x * 128;
    int tx = tid & 15;
    int ty = tid >> 4;

    int arow = tid >> 1;
    int acol = (tid & 1) * 4;
    const float* Abase;
    if (amode == 1) {
        int tb = row0 + arow;
        int t = tb >> 8, b = tb & 255;
        Abase = A + ((size_t)b * TT + t) * NINW;
    } else {
        Abase = A + (size_t)(row0 + arow) * K;
    }
    int brow = tid >> 5;
    int bcol = (tid & 31) * 4;
    const float* Bbase = W + (size_t)brow * N + col0 + bcol;

    float acc[8][8];
    #pragma unroll
    for (int i = 0; i < 8; i++)
        #pragma unroll
        for (int j = 0; j < 8; j++) acc[i][j] = 0.f;

    // prologue: chunk 0 -> smem
    {
        float4 av = *(const float4*)(Abase + acol);
        float4 bv = *(const float4*)(Bbase);
        As[acol + 0][arow] = av.x;
        As[acol + 1][arow] = av.y;
        As[acol + 2][arow] = av.z;
        As[acol + 3][arow] = av.w;
        *(float4*)&Bs[brow][bcol] = bv;
    }
    __syncthreads();

    for (int k0 = 0; k0 < K; k0 += 8) {
        bool more = (k0 + 8) < K;
        float4 avn, bvn;
        if (more) {
            avn = *(const float4*)(Abase + k0 + 8 + acol);
            bvn = *(const float4*)(Bbase + (size_t)(k0 + 8) * N);
        }

        #pragma unroll
        for (int kk = 0; kk < 8; kk++) {
            float a[8], bb[8];
            *(float4*)&a[0]  = *(const float4*)&As[kk][ty * 8];
            *(float4*)&a[4]  = *(const float4*)&As[kk][ty * 8 + 4];
            *(float4*)&bb[0] = *(const float4*)&Bs[kk][tx * 8];
            *(float4*)&bb[4] = *(const float4*)&Bs[kk][tx * 8 + 4];
            #pragma unroll
            for (int i = 0; i < 8; i++)
                #pragma unroll
                for (int j = 0; j < 8; j++)
                    acc[i][j] = fmaf(a[i], bb[j], acc[i][j]);
        }

        __syncthreads();            // everyone done reading this chunk
        if (more) {
            As[acol + 0][arow] = avn.x;
            As[acol + 1][arow] = avn.y;
            As[acol + 2][arow] = avn.z;
            As[acol + 3][arow] = avn.w;
            *(float4*)&Bs[brow][bcol] = bvn;
        }
        __syncthreads();            // next chunk visible
    }

    float bia[8];
    #pragma unroll
    for (int j = 0; j < 8; j++) bia[j] = bias[col0 + tx * 8 + j];

    #pragma unroll
    for (int i = 0; i < 8; i++) {
        size_t r = (size_t)(row0 + ty * 8 + i);
        float* cp = C + r * N + col0 + tx * 8;
        float4 v0 = make_float4(acc[i][0] + bia[0], acc[i][1] + bia[1],
                                acc[i][2] + bia[2], acc[i][3] + bia[3]);
        float4 v1 = make_float4(acc[i][4] + bia[4], acc[i][5] + bia[5],
                                acc[i][6] + bia[6], acc[i][7] + bia[7]);
        *(float4*)(cp)     = v0;
        *(float4*)(cp + 4) = v1;
    }
}

// ---------------------------------------------------------------------------
// Fused per-timestep BatchNorm (training stats over B=256) + ELU, in place.
// ---------------------------------------------------------------------------
__global__ void bn_elu(int sel, const float* __restrict__ g, const float* __restrict__ be) {
    float* X = devBuf(sel);
    int t  = blockIdx.x;
    int jl = threadIdx.x & 63;
    int grp = threadIdx.x >> 6;
    int j = blockIdx.y * 64 + jl;

    float s = 0.f, s2 = 0.f;
    int brow0 = grp * 64;
    #pragma unroll 4
    for (int b = brow0; b < brow0 + 64; b++) {
        float v = X[((size_t)t * BB + b) * HH + j];
        s += v;
        s2 = fmaf(v, v, s2);
    }
    __shared__ float ss[4][64], sq[4][64], mu[64], rs[64];
    ss[grp][jl] = s;
    sq[grp][jl] = s2;
    __syncthreads();
    if (threadIdx.x < 64) {
        float S  = ss[0][jl] + ss[1][jl] + ss[2][jl] + ss[3][jl];
        float S2 = sq[0][jl] + sq[1][jl] + sq[2][jl] + sq[3][jl];
        float m = S * (1.f / 256.f);
        float var = S2 * (1.f / 256.f) - m * m;
        mu[jl] = m;
        rs[jl] = rsqrtf(var + 1e-5f);
    }
    __syncthreads();
    float m = mu[jl], r = rs[jl], gg = g[j], bb = be[j];
    #pragma unroll 4
    for (int b = brow0; b < brow0 + 64; b++) {
        size_t idx = ((size_t)t * BB + b) * HH + j;
        float v = gg * (X[idx] - m) * r + bb;
        X[idx] = v > 0.f ? v : expm1f(v);
    }
}

// ---------------------------------------------------------------------------
// FUSED recurrence, pipelined:
//   64 blocks x 256 threads; block owns 4 batch rows; h (+a_prev) in smem.
//   - Wq streamed in 8-k chunks, double-buffered in registers (LDG 8 deep)
//   - h read as float4 broadcasts (4 LDS.128 per chunk per row-pack)
//   - GI / AE global loads prefetched BEFORE the gate GEMM of each step
// ---------------------------------------------------------------------------
__global__ void __launch_bounds__(256, 1)
gru_fused(float* __restrict__ outFinal) {
    __shared__ float hA[4][288];     // [b-row][k]  k<256: h, 256..271: a_prev

    const int e  = threadIdx.x;      // 0..255
    const int b0 = blockIdx.x * 4;

    #pragma unroll
    for (int r = 0; r < 4; r++) {
        hA[r][e] = 0.f;
        if (e < 32) hA[r][256 + e] = 0.f;
    }
    __syncthreads();

    const float4 bc = d_bcg4[e];
    const float4* __restrict__ Wq = d_Wq4;

    for (int t = 0; t < TT; t++) {
        // ---- prefetch this step's independent global data (hides DRAM) ----
        float ir[4], iz[4], inn[4];
        {
            const float* GIt = d_GI + (size_t)t * BB * NG;
            #pragma unroll
            for (int r = 0; r < 4; r++) {
                const float* gi = GIt + (size_t)(b0 + r) * NG;
                ir[r]  = gi[e];
                iz[r]  = gi[EE + e];
                inn[r] = gi[2 * EE + e];
            }
        }
        float aePf = 0.f;
        if (t < TT - 1 && e < 64)
            aePf = d_AE[((size_t)t * BB + b0 + (e >> 4)) * AA + (e & 15)];

        // ---- gate GEMM: acc[r] = sum_k hA[r][k] * Wq[k][e] (4 gates) ----
        float4 acc0 = make_float4(0.f, 0.f, 0.f, 0.f);
        float4 acc1 = acc0, acc2 = acc0, acc3 = acc0;

        float4 w0[8], w1[8];
        #pragma unroll
        for (int i = 0; i < 8; i++) w0[i] = Wq[i * EE + e];

        #pragma unroll 1
        for (int kc = 0; kc < KHE / 8; kc++) {          // 34 chunks
            float4* wc = (kc & 1) ? w1 : w0;
            float4* wn = (kc & 1) ? w0 : w1;
            if (kc < KHE / 8 - 1) {
                int kb = (kc + 1) * 8;
                #pragma unroll
                for (int i = 0; i < 8; i++) wn[i] = Wq[(kb + i) * EE + e];
            }
            int kb = kc * 8;
            float h0[4][8];
            #pragma unroll
            for (int r = 0; r < 4; r++) {
                *(float4*)&h0[r][0] = *(const float4*)&hA[r][kb];
                *(float4*)&h0[r][4] = *(const float4*)&hA[r][kb + 4];
            }
            #pragma unroll
            for (int i = 0; i < 8; i++) {
                float4 w = wc[i];
                acc0.x = fmaf(h0[0][i], w.x, acc0.x);
                acc0.y = fmaf(h0[0][i], w.y, acc0.y);
                acc0.z = fmaf(h0[0][i], w.z, acc0.z);
                acc0.w = fmaf(h0[0][i], w.w, acc0.w);
                acc1.x = fmaf(h0[1][i], w.x, acc1.x);
                acc1.y = fmaf(h0[1][i], w.y, acc1.y);
                acc1.z = fmaf(h0[1][i], w.z, acc1.z);
                acc1.w = fmaf(h0[1][i], w.w, acc1.w);
                acc2.x = fmaf(h0[2][i], w.x, acc2.x);
                acc2.y = fmaf(h0[2][i], w.y, acc2.y);
                acc2.z = fmaf(h0[2][i], w.z, acc2.z);
                acc2.w = fmaf(h0[2][i], w.w, acc2.w);
                acc3.x = fmaf(h0[3][i], w.x, acc3.x);
                acc3.y = fmaf(h0[3][i], w.y, acc3.y);
                acc3.z = fmaf(h0[3][i], w.z, acc3.z);
                acc3.w = fmaf(h0[3][i], w.w, acc3.w);
            }
        }

        // ---- GRU elementwise ----
        float hnew[4];
        {
            float4 acc[4] = {acc0, acc1, acc2, acc3};
            #pragma unroll
            for (int r = 0; r < 4; r++) {
                float henc = acc[r].x + bc.x;
                float hr   = acc[r].y + bc.y;
                float hz   = acc[r].z + bc.z;
                float hn   = acc[r].w + bc.w;
                float rg = 1.f / (1.f + expf(-(ir[r] + hr)));
                float zg = 1.f / (1.f + expf(-(iz[r] + hz)));
                float ng = tanhf(inn[r] + rg * hn);
                hnew[r] = (1.f - zg) * ng + zg * henc;
            }
        }

        if (t == TT - 1) {
            #pragma unroll
            for (int r = 0; r < 4; r++)
                outFinal[(size_t)(b0 + r) * EE + e] = hnew[r];
            break;
        }

        __syncthreads();             // all reads of hA done
        #pragma unroll
        for (int r = 0; r < 4; r++) hA[r][e] = hnew[r];
        if (e < 64) hA[e >> 4][256 + (e & 15)] = aePf;
        __syncthreads();
    }
}

// ---------------------------------------------------------------------------
// Host launch (graph-capturable: kernel launches only)
// ---------------------------------------------------------------------------
extern "C" void kernel_launch(void* const* d_in, const int* in_sizes, int n_in,
                              void* d_out, int out_size) {
    const float* obs     = (const float*)d_in[0];
    const float* actions = (const float*)d_in[1];
    const float* W1  = (const float*)d_in[2];
    const float* b1  = (const float*)d_in[3];
    const float* g1  = (const float*)d_in[4];
    const float* be1 = (const float*)d_in[5];
    const float* W2  = (const float*)d_in[6];
    const float* b2  = (const float*)d_in[7];
    const float* g2  = (const float*)d_in[8];
    const float* be2 = (const float*)d_in[9];
    const float* W3  = (const float*)d_in[10];
    const float* b3  = (const float*)d_in[11];
    const float* Wih = (const float*)d_in[12];
    const float* bih = (const float*)d_in[13];
    const float* Whh = (const float*)d_in[14];
    const float* bhh = (const float*)d_in[15];
    const float* Whe = (const float*)d_in[16];
    const float* bhe = (const float*)d_in[17];
    const float* Wae = (const float*)d_in[18];
    const float* bae = (const float*)d_in[19];
    float* out = (float*)d_out;

    // One-time-per-launch prep (recomputed every call: deterministic)
    prep_wq<<<KHE, 256>>>(Whe, bhe, Whh, bhh);
    prep_fold<<<dim3(NG / 256, HH), 256>>>(W3, b3, Wih, bih);
    prep_ae<<<(TT * BB * AA) / 256, 256>>>(actions, Wae, bae);

    // Batched MLP + GRU input path (all timesteps in parallel)
    sgemm_k<<<dim3(HH / 128, MROWS / 128), 256>>>(obs, 0, W1, b1, 1, MROWS, HH, NINW, 1);
    bn_elu<<<dim3(TT, HH / 64), 256>>>(1, g1, be1);
    sgemm_k<<<dim3(HH / 128, MROWS / 128), 256>>>(nullptr, 1, W2, b2, 2, MROWS, HH, HH, 0);
    bn_elu<<<dim3(TT, HH / 64), 256>>>(2, g2, be2);
    // Folded (W3@Wih) GEMM: X2 -> GI directly
    sgemm_k<<<dim3(NG / 128, MROWS / 128), 256>>>(nullptr, 2, nullptr, nullptr, 4, MROWS, NG, HH, 0);

    // Entire GRU recurrence in ONE persistent kernel (batch-diagonal)
    gru_fused<<<64, 256>>>(out);
}